// round 15
// baseline (speedup 1.0000x reference)
#include <cuda_runtime.h>
#include <cuda.h>
#include <cstdint>

// FMFMNeuronInhib: T=4096, B=4096.  x:[T][B][2] f32.  out = spk|exc|inh|mem.
//
// TMA-everything pipeline. 128 blocks x 128 threads (4 warps), 32 neurons per
// block, one block per SM, ~152 KB dynamic smem:
//   warp 3       : exact sequential mem recurrence (also computes spk)
//   warps 0-1    : map staged x chunk -> excbuf (smem->smem, float4)
//   warp 2 (t64) : TMA control — bulk-tensor load of x chunk c+2 (3-deep ring,
//                  mbarrier) + bulk-tensor stores of mem/spk/exc (4-deep ring)
//                  and inh (constant zero buffer), bulk_group flow control.
// All global traffic runs through the TMA engine: no register staging, no
// per-warp MLP limits. x read from DRAM exactly once; traffic = 384 MB.
// Fast path exact for winh==0 (fma(0,inh,exc)==exc, 0*inh==+0);
// generic winh!=0 handled by an exact in-kernel fallback.

#define T_STEPS 4096
#define B_NEUR  4096
#define CH      64
#define NCH     (T_STEPS / CH)       // 64
#define XRING   3
#define OB      4
#define THREADS 128
#define TMA_TID 64

#define XSLOT   (CH * 64 * 4)        // 16384 B  (64 steps x 64 floats)
#define OSLOT   (CH * 32 * 4)        //  8192 B  (64 steps x 32 floats)
#define XO      0
#define MO      (XRING * XSLOT)                  // 49152
#define SO      (MO + OB * OSLOT)                // 81920
#define EO      (SO + OB * OSLOT)                // 114688
#define ZO      (EO + OB * OSLOT)                // 147456
#define BARO    (ZO + OSLOT)                     // 155648
#define SMEM_BYTES (BARO + 64)                   // 155712

// ---------------- PTX helpers ----------------
#define MBAR_INIT(a, n) \
    asm volatile("mbarrier.init.shared.b64 [%0], %1;" :: "r"(a), "r"(n) : "memory")
#define MBAR_EXPECT(a, bytes) \
    asm volatile("mbarrier.arrive.expect_tx.shared.b64 _, [%0], %1;" \
                 :: "r"(a), "r"(bytes) : "memory")

__device__ __forceinline__ void mbar_wait(uint32_t a, uint32_t ph) {
    uint32_t done;
    do {
        asm volatile(
            "{\n\t.reg .pred p;\n\t"
            "mbarrier.try_wait.parity.acquire.cta.shared::cta.b64 p, [%1], %2, 0x989680;\n\t"
            "selp.b32 %0, 1, 0, p;\n\t}"
            : "=r"(done) : "r"(a), "r"(ph) : "memory");
    } while (!done);
}

#define TMA_LOAD2D(smem, map, cx, cy, mbar) \
    asm volatile("cp.async.bulk.tensor.2d.shared::cta.global.tile.mbarrier::complete_tx::bytes " \
                 "[%0], [%1, {%2, %3}], [%4];" \
                 :: "r"(smem), "l"(map), "r"(cx), "r"(cy), "r"(mbar) : "memory")
#define TMA_STORE2D(map, cx, cy, smem) \
    asm volatile("cp.async.bulk.tensor.2d.global.shared::cta.tile.bulk_group " \
                 "[%0, {%1, %2}], [%3];" \
                 :: "l"(map), "r"(cx), "r"(cy), "r"(smem) : "memory")
#define BULK_COMMIT() asm volatile("cp.async.bulk.commit_group;" ::: "memory")
#define BULK_WAIT(n)  asm volatile("cp.async.bulk.wait_group.read %0;" :: "n"(n) : "memory")
#define FENCE_ASYNC() asm volatile("fence.proxy.async.shared::cta;" ::: "memory")

// ---------------- main kernel ----------------
__global__ __launch_bounds__(THREADS, 1)
void fmfm_tma(const float* __restrict__ x,
              const float* __restrict__ w_exc,
              const float* __restrict__ w_inh_p,
              float* __restrict__ out,
              const __grid_constant__ CUtensorMap mx,
              const __grid_constant__ CUtensorMap mmem,
              const __grid_constant__ CUtensorMap mspk,
              const __grid_constant__ CUtensorMap mexc,
              const __grid_constant__ CUtensorMap minh)
{
    extern __shared__ __align__(128) char dyn[];
    const int tid  = threadIdx.x;
    const int wid  = tid >> 5;
    const int lane = tid & 31;
    const int b0   = blockIdx.x * 32;

    const float w00  = w_exc[0];
    const float w01  = w_exc[1];
    const float winh = *w_inh_p;

    // ---------------- generic fallback (winh != 0): exact, never taken here
    if (winh != 0.0f) {
        if (tid < 32) {
            const int b = b0 + tid;
            const float2* __restrict__ xq = reinterpret_cast<const float2*>(x) + b;
            float* __restrict__ O_spk = out;
            float* __restrict__ O_exc = out + (size_t)T_STEPS * B_NEUR;
            float* __restrict__ O_inh = out + 2ull * T_STEPS * B_NEUR;
            float* __restrict__ O_mem = out + 3ull * T_STEPS * B_NEUR;
            float mem = 0.0f, inh = 0.0f;
            for (int t = 0; t < T_STEPS; t++) {
                const float2 v = xq[(size_t)t * B_NEUR];
                inh = __fmaf_rn(0.6f, inh, v.x);
                const float exc = __fmaf_rn(v.y, w01, __fmul_rn(v.x, w00));
                const float cur = __fmaf_rn(winh, inh, exc);
                const float reset = (mem > 1.0f) ? 1.0f : 0.0f;
                mem = __fsub_rn(__fadd_rn(__fmul_rn(0.9f, mem), cur), reset);
                const size_t off = (size_t)t * B_NEUR + b;
                O_spk[off] = (__fsub_rn(mem, 1.0f) > 0.0f) ? 1.0f : 0.0f;
                O_exc[off] = exc;
                O_inh[off] = __fmul_rn(winh, inh);
                O_mem[off] = mem;
            }
        }
        return;
    }

    // ---------------- fast path (winh == 0) ----------------
    const uint32_t sbase = (uint32_t)__cvta_generic_to_shared(dyn);

    // prologue: mbarriers, zero buffer (inh output), first two x chunk loads
    if (tid == TMA_TID) {
        MBAR_INIT(sbase + BARO + 0, 1);
        MBAR_INIT(sbase + BARO + 8, 1);
        MBAR_INIT(sbase + BARO + 16, 1);
    }
    for (int i = tid; i < CH * 32; i += THREADS)
        reinterpret_cast<float*>(dyn + ZO)[i] = 0.0f;
    __syncthreads();
    if (tid == TMA_TID) {
        MBAR_EXPECT(sbase + BARO + 0, XSLOT);
        TMA_LOAD2D(sbase + XO,         &mx, b0 * 2, 0,  sbase + BARO + 0);
        MBAR_EXPECT(sbase + BARO + 8, XSLOT);
        TMA_LOAD2D(sbase + XO + XSLOT, &mx, b0 * 2, CH, sbase + BARO + 8);
        mbar_wait(sbase + BARO + 0, 0);      // chunk 0 resident
    }
    __syncthreads();

    if (wid == 3) {
        // ======== chain warp: exact mem recurrence + spk ========
        float mem = 0.0f;
        for (int c = 0; c < NCH; c++) {
            const float2* __restrict__ xb =
                reinterpret_cast<const float2*>(dyn + XO + (c % XRING) * XSLOT);
            float* __restrict__ mb = reinterpret_cast<float*>(dyn + MO + (c & 3) * OSLOT);
            float* __restrict__ sb = reinterpret_cast<float*>(dyn + SO + (c & 3) * OSLOT);
            #pragma unroll
            for (int k = 0; k < CH; k += 16) {
                float2 v[16];
                #pragma unroll
                for (int i = 0; i < 16; i++)
                    v[i] = xb[(k + i) * 32 + lane];
                #pragma unroll
                for (int i = 0; i < 16; i++) {
                    // cur == exc exactly when winh==0
                    const float cur = __fmaf_rn(v[i].y, w01, __fmul_rn(v[i].x, w00));
                    const float reset = (mem > 1.0f) ? 1.0f : 0.0f;
                    mem = __fsub_rn(__fadd_rn(__fmul_rn(0.9f, mem), cur), reset);
                    mb[(k + i) * 32 + lane] = mem;
                    sb[(k + i) * 32 + lane] =
                        (__fsub_rn(mem, 1.0f) > 0.0f) ? 1.0f : 0.0f;
                }
            }
            __syncthreads();
        }
    } else if (wid < 2) {
        // ======== exc warps: map staged x chunk -> excbuf (float4) ========
        const int sl = lane >> 3;      // 0..3 step-in-quad
        const int n4 = lane & 7;       // 0..7 neuron-quad
        const int w  = wid;
        for (int c = 0; c < NCH; c++) {
            const float4* __restrict__ xb4 =
                reinterpret_cast<const float4*>(dyn + XO + (c % XRING) * XSLOT);
            float4* __restrict__ eb4 =
                reinterpret_cast<float4*>(dyn + EO + (c & 3) * OSLOT);
            #pragma unroll
            for (int it = 0; it < 8; it++) {
                const int s = it * 8 + w * 4 + sl;
                const float4 a  = xb4[s * 16 + n4 * 2];      // neurons 4n4, 4n4+1
                const float4 bq = xb4[s * 16 + n4 * 2 + 1];  // neurons 4n4+2, 4n4+3
                float4 e;
                e.x = __fmaf_rn(a.y,  w01, __fmul_rn(a.x,  w00));
                e.y = __fmaf_rn(a.w,  w01, __fmul_rn(a.z,  w00));
                e.z = __fmaf_rn(bq.y, w01, __fmul_rn(bq.x, w00));
                e.w = __fmaf_rn(bq.w, w01, __fmul_rn(bq.z, w00));
                eb4[s * 8 + n4] = e;
            }
            __syncthreads();
        }
    } else {
        // ======== TMA control warp ========
        for (int c = 0; c < NCH; c++) {
            if (tid == TMA_TID) {
                FENCE_ASYNC();             // order generic smem accesses vs async proxy
                if (c > 0) {               // store chunk c-1 (staged last period)
                    const int k = c - 1, t0 = k * CH, ko = (k & 3) * OSLOT;
                    TMA_STORE2D(&mmem, b0, t0, sbase + MO + ko);
                    TMA_STORE2D(&mspk, b0, t0, sbase + SO + ko);
                    TMA_STORE2D(&mexc, b0, t0, sbase + EO + ko);
                    TMA_STORE2D(&minh, b0, t0, sbase + ZO);
                    BULK_COMMIT();
                }
                const int cf = c + 2;      // load chunk c+2
                if (cf < NCH) {
                    const uint32_t bar = sbase + BARO + (cf % XRING) * 8;
                    MBAR_EXPECT(bar, XSLOT);
                    TMA_LOAD2D(sbase + XO + (cf % XRING) * XSLOT,
                               &mx, b0 * 2, cf * CH, bar);
                }
                BULK_WAIT(2);              // groups <= c-3 read-done: obuf[(c+1)&3] free
                if (c + 1 < NCH)           // chunk c+1 resident before next period
                    mbar_wait(sbase + BARO + ((c + 1) % XRING) * 8,
                              (uint32_t)(((c + 1) / XRING) & 1));
            }
            __syncthreads();
        }
        if (tid == TMA_TID) {              // epilogue: last chunk
            FENCE_ASYNC();
            const int k = NCH - 1, t0 = k * CH, ko = (k & 3) * OSLOT;
            TMA_STORE2D(&mmem, b0, t0, sbase + MO + ko);
            TMA_STORE2D(&mspk, b0, t0, sbase + SO + ko);
            TMA_STORE2D(&mexc, b0, t0, sbase + EO + ko);
            TMA_STORE2D(&minh, b0, t0, sbase + ZO);
            BULK_COMMIT();
            BULK_WAIT(0);
        }
    }
}

// ---------------- contingency kernel (tensor-map creation failed) ----------
__global__ __launch_bounds__(32)
void fmfm_simple(const float* __restrict__ x,
                 const float* __restrict__ w_exc,
                 const float* __restrict__ w_inh_p,
                 float* __restrict__ out)
{
    const int b = blockIdx.x * 32 + threadIdx.x;
    const float w00 = w_exc[0], w01 = w_exc[1], winh = *w_inh_p;
    const float2* __restrict__ xq = reinterpret_cast<const float2*>(x) + b;
    float* __restrict__ O_spk = out;
    float* __restrict__ O_exc = out + (size_t)T_STEPS * B_NEUR;
    float* __restrict__ O_inh = out + 2ull * T_STEPS * B_NEUR;
    float* __restrict__ O_mem = out + 3ull * T_STEPS * B_NEUR;
    float mem = 0.0f, inh = 0.0f;
    for (int t0 = 0; t0 < T_STEPS; t0 += 8) {
        float2 v[8];
        #pragma unroll
        for (int i = 0; i < 8; i++) v[i] = xq[(size_t)(t0 + i) * B_NEUR];
        #pragma unroll
        for (int i = 0; i < 8; i++) {
            inh = __fmaf_rn(0.6f, inh, v[i].x);
            const float exc = __fmaf_rn(v[i].y, w01, __fmul_rn(v[i].x, w00));
            const float cur = __fmaf_rn(winh, inh, exc);
            const float reset = (mem > 1.0f) ? 1.0f : 0.0f;
            mem = __fsub_rn(__fadd_rn(__fmul_rn(0.9f, mem), cur), reset);
            const size_t off = (size_t)(t0 + i) * B_NEUR + b;
            O_spk[off] = (__fsub_rn(mem, 1.0f) > 0.0f) ? 1.0f : 0.0f;
            O_exc[off] = exc;
            O_inh[off] = __fmul_rn(winh, inh);
            O_mem[off] = mem;
        }
    }
}

// ---------------- host: tensor maps + launch ----------------
typedef CUresult (*EncodeFn)(CUtensorMap*, CUtensorMapDataType, cuuint32_t, void*,
                             const cuuint64_t*, const cuuint64_t*,
                             const cuuint32_t*, const cuuint32_t*,
                             CUtensorMapInterleave, CUtensorMapSwizzle,
                             CUtensorMapL2promotion, CUtensorMapFloatOOBfill);

static bool build_maps(const float* x, float* out, CUtensorMap maps[5])
{
    static EncodeFn enc = nullptr;
    if (!enc) {
        void* fn = nullptr;
        cudaDriverEntryPointQueryResult q;
        if (cudaGetDriverEntryPointByVersion("cuTensorMapEncodeTiled", &fn, 12000,
                                             cudaEnableDefault, &q) != cudaSuccess ||
            q != cudaDriverEntryPointSuccess || fn == nullptr)
            return false;
        enc = (EncodeFn)fn;
    }
    cuuint32_t es[2] = {1, 1};
    // x: [4096 rows][8192 floats], box {64, CH}
    {
        cuuint64_t d[2] = {8192, 4096};
        cuuint64_t s[1] = {8192ull * 4};
        cuuint32_t bx[2] = {64, CH};
        if (enc(&maps[0], CU_TENSOR_MAP_DATA_TYPE_FLOAT32, 2, (void*)x, d, s, bx, es,
                CU_TENSOR_MAP_INTERLEAVE_NONE, CU_TENSOR_MAP_SWIZZLE_NONE,
                CU_TENSOR_MAP_L2_PROMOTION_L2_128B,
                CU_TENSOR_MAP_FLOAT_OOB_FILL_NONE) != CUDA_SUCCESS)
            return false;
    }
    // outputs: each [4096 rows][4096 floats], box {32, CH}
    float* bases[4] = {
        out + 3ull * T_STEPS * B_NEUR,   // mem
        out,                              // spk
        out + 1ull * T_STEPS * B_NEUR,   // exc
        out + 2ull * T_STEPS * B_NEUR    // inh
    };
    for (int i = 0; i < 4; i++) {
        cuuint64_t d[2] = {4096, 4096};
        cuuint64_t s[1] = {4096ull * 4};
        cuuint32_t bx[2] = {32, CH};
        if (enc(&maps[1 + i], CU_TENSOR_MAP_DATA_TYPE_FLOAT32, 2, (void*)bases[i],
                d, s, bx, es,
                CU_TENSOR_MAP_INTERLEAVE_NONE, CU_TENSOR_MAP_SWIZZLE_NONE,
                CU_TENSOR_MAP_L2_PROMOTION_L2_128B,
                CU_TENSOR_MAP_FLOAT_OOB_FILL_NONE) != CUDA_SUCCESS)
            return false;
    }
    return true;
}

extern "C" void kernel_launch(void* const* d_in, const int* in_sizes, int n_in,
                              void* d_out, int out_size)
{
    const float* x     = (const float*)d_in[0];
    const float* w_exc = (const float*)d_in[1];
    const float* w_inh = (const float*)d_in[2];
    float* out         = (float*)d_out;
    (void)in_sizes; (void)n_in; (void)out_size;

    static const float* last_x = nullptr;
    static float* last_out = nullptr;
    static CUtensorMap maps[5];
    static bool maps_ok = false;
    static bool attr_set = false;

    if (x != last_x || out != last_out) {
        maps_ok = build_maps(x, out, maps);
        last_x = x; last_out = out;
    }

    if (maps_ok) {
        if (!attr_set) {
            cudaFuncSetAttribute(fmfm_tma,
                                 cudaFuncAttributeMaxDynamicSharedMemorySize,
                                 SMEM_BYTES);
            attr_set = true;
        }
        fmfm_tma<<<B_NEUR / 32, THREADS, SMEM_BYTES>>>(
            x, w_exc, w_inh, out, maps[0], maps[1], maps[2], maps[3], maps[4]);
    } else {
        fmfm_simple<<<B_NEUR / 32, 32>>>(x, w_exc, w_inh, out);
    }
}

// round 16
// speedup vs baseline: 1.1201x; 1.1201x over previous
#include <cuda_runtime.h>
#include <cstdint>

// FMFMNeuronInhib: T=4096, B=4096.  x:[T][B][2] f32.  out = spk|exc|inh|mem.
//
// Single-pass warp-specialized kernel. 128 blocks x 512 threads (16 warps),
// 32 neurons per block, one block per SM, 128 KB dynamic smem.
// SMSP-aware role map (wid%4 = SMSP):
//   wid 13            : exact mem-recurrence chain — ALONE on SMSP 1
//   wids 1, 5, 9      : idle (barrier-only) — keep SMSP 1 clear of HOLD bursts
//   r(wid) in 0..3    : mem/spk writers  (drain membuf chunk c-1, scalar STG)
//   r(wid) in 4..7    : exc/inh writers  (map staged x chunk c, scalar STG)
//   r(wid) in 8..11   : cp.async(16B) prefetch of x chunk c+2 into 3-deep ring
// CH=128 steps/chunk (32 barrier periods). x read from DRAM exactly once;
// traffic = 384 MB. Chain arithmetic identical to prior passing kernels.
// Fast path exact for winh==0 (fma(0,inh,exc)==exc, 0*inh==+0);
// generic winh!=0 handled by an exact (slow, never-taken here) fallback.

#define T_STEPS 4096
#define B_NEUR  4096
#define CH      128                  // steps per smem chunk
#define NCH     (T_STEPS / CH)       // 32
#define XRING   3                    // x ring depth (prefetch 2 ahead)
#define THREADS 512

#define XCHUNK_ELEMS (CH * 32)                        // float2 per chunk
#define XBYTES   (XRING * XCHUNK_ELEMS * 8)           // 96 KB
#define MBYTES   (2 * XCHUNK_ELEMS * 4)               // 32 KB
#define SMEM_BYTES (XBYTES + MBYTES)                  // 128 KB

#define CP_ASYNC16(sa, g) \
    asm volatile("cp.async.ca.shared.global [%0], [%1], 16;" :: "r"(sa), "l"(g))
#define CP_COMMIT()  asm volatile("cp.async.commit_group;" ::: "memory")
#define CP_WAIT1()   asm volatile("cp.async.wait_group 1;" ::: "memory")

__global__ __launch_bounds__(THREADS, 1)
void fmfm_onepass(const float* __restrict__ x,
                  const float* __restrict__ w_exc,
                  const float* __restrict__ w_inh_p,
                  float* __restrict__ out)
{
    extern __shared__ char dynsmem[];
    float2* const xbuf   = reinterpret_cast<float2*>(dynsmem);           // [XRING][CH*32]
    float*  const membuf = reinterpret_cast<float*>(dynsmem + XBYTES);   // [2][CH*32]

    const int tid  = threadIdx.x;
    const int wid  = tid >> 5;
    const int lane = tid & 31;
    const int b    = blockIdx.x * 32 + lane;
    const int b0   = blockIdx.x * 32;

    const float w00  = w_exc[0];
    const float w01  = w_exc[1];
    const float winh = *w_inh_p;

    float* __restrict__ O_spk = out;
    float* __restrict__ O_exc = out + (size_t)T_STEPS * B_NEUR;
    float* __restrict__ O_inh = out + 2ull * T_STEPS * B_NEUR;
    float* __restrict__ O_mem = out + 3ull * T_STEPS * B_NEUR;

    const float2* __restrict__ x2 = reinterpret_cast<const float2*>(x);
    const float2* __restrict__ xw = x2 + b;

    // ---------------- generic fallback (winh != 0): exact, never taken here
    if (winh != 0.0f) {
        if (tid < 32) {
            float mem = 0.0f, inh = 0.0f;
            for (int t = 0; t < T_STEPS; t++) {
                const float2 v = xw[(size_t)t * B_NEUR];
                inh = __fmaf_rn(0.6f, inh, v.x);
                const float exc = __fmaf_rn(v.y, w01, __fmul_rn(v.x, w00));
                const float cur = __fmaf_rn(winh, inh, exc);
                const float reset = (mem > 1.0f) ? 1.0f : 0.0f;
                mem = __fsub_rn(__fadd_rn(__fmul_rn(0.9f, mem), cur), reset);
                const size_t off = (size_t)t * B_NEUR + b;
                O_spk[off] = (__fsub_rn(mem, 1.0f) > 0.0f) ? 1.0f : 0.0f;
                O_exc[off] = exc;
                O_inh[off] = __fmul_rn(winh, inh);
                O_mem[off] = mem;
            }
        }
        return;
    }

    // ---------------- fast path (winh == 0) ----------------
    // Role map: wid 13 = chain (sole occupant of SMSP 1); wids 1,5,9 idle;
    // remaining 12 warps get compact role index r in 0..11.
    const bool is_chain = (wid == 13);
    const bool is_idle  = (wid == 1) || (wid == 5) || (wid == 9);
    const int r = wid - (wid >= 2) - (wid >= 6) - (wid >= 10) - (wid >= 14);

    if (is_chain) {
        // ======== chain warp: exact mem recurrence (SMSP 1, uncontended) ====
        float mem = 0.0f;
        __syncthreads();            // prologue barrier: chunk 0 staged
        for (int c = 0; c < NCH; c++) {
            const float2* __restrict__ xb = xbuf + (c % XRING) * XCHUNK_ELEMS;
            float* __restrict__       mb = membuf + (c & 1) * XCHUNK_ELEMS;
            #pragma unroll
            for (int k = 0; k < CH; k += 16) {
                float2 v[16];
                #pragma unroll
                for (int i = 0; i < 16; i++)
                    v[i] = xb[(k + i) * 32 + lane];
                #pragma unroll
                for (int i = 0; i < 16; i++) {
                    // cur == exc exactly when winh==0
                    const float cur = __fmaf_rn(v[i].y, w01, __fmul_rn(v[i].x, w00));
                    const float reset = (mem > 1.0f) ? 1.0f : 0.0f;
                    mem = __fsub_rn(__fadd_rn(__fmul_rn(0.9f, mem), cur), reset);
                    mb[(k + i) * 32 + lane] = mem;
                }
            }
            __syncthreads();
        }
    } else if (is_idle) {
        // ======== idle warps (wids 1,5,9): keep SMSP 1 clear ========
        __syncthreads();            // prologue barrier
        for (int c = 0; c < NCH; c++)
            __syncthreads();
    } else if (r >= 8) {
        // ======== prefetch warps (r 8..11): 16B cp.async chunk c+2 ========
        // lane -> (step-in-pair, neuron-pair): 2 steps x 32 neurons per op row
        const int p   = r - 8;
        const int sp  = lane >> 4;           // 0..1
        const int npr = lane & 15;           // 0..15 (neurons 2*npr, 2*npr+1)
        const float2* __restrict__ gsrc = x2 + b0 + npr * 2;
        // prologue: chunks 0,1 -> one commit group each
        #pragma unroll
        for (int k = 0; k < 2; k++) {
            float2* __restrict__ xb = xbuf + k * XCHUNK_ELEMS;
            for (int s2 = p; s2 < CH / 2; s2 += 4) {
                const int s = s2 * 2 + sp;
                const float2* g = gsrc + (size_t)(k * CH + s) * B_NEUR;
                const uint32_t sa =
                    (uint32_t)__cvta_generic_to_shared(&xb[s * 32 + npr * 2]);
                CP_ASYNC16(sa, g);
            }
            CP_COMMIT();
        }
        CP_WAIT1();                 // chunk 0 resident
        __syncthreads();
        for (int c = 0; c < NCH; c++) {
            const int cf = c + 2;
            if (cf < NCH) {
                const int t0 = cf * CH;
                float2* __restrict__ xb = xbuf + (cf % XRING) * XCHUNK_ELEMS;
                for (int s2 = p; s2 < CH / 2; s2 += 4) {
                    const int s = s2 * 2 + sp;
                    const float2* g = gsrc + (size_t)(t0 + s) * B_NEUR;
                    const uint32_t sa =
                        (uint32_t)__cvta_generic_to_shared(&xb[s * 32 + npr * 2]);
                    CP_ASYNC16(sa, g);
                }
            }
            CP_COMMIT();            // (possibly empty) group keeps indexing uniform
            CP_WAIT1();             // all but newest done -> chunk c+1 resident
            __syncthreads();
        }
    } else if (r < 4) {
        // ======== mem/spk writers (r 0..3): drain chunk c-1, 32 steps each ==
        const int w = r;
        __syncthreads();            // prologue barrier
        for (int c = 0; c < NCH; c++) {
            if (c > 0) {
                const float* __restrict__ mb = membuf + ((c - 1) & 1) * XCHUNK_ELEMS;
                const int t0 = (c - 1) * CH;
                #pragma unroll
                for (int s = w * 32; s < w * 32 + 32; s++) {
                    const float m = mb[s * 32 + lane];
                    const size_t off = (size_t)(t0 + s) * B_NEUR + b;
                    __stcs(O_mem + off, m);
                    __stcs(O_spk + off, (__fsub_rn(m, 1.0f) > 0.0f) ? 1.0f : 0.0f);
                }
            }
            __syncthreads();
        }
        {   // epilogue: last chunk
            const float* __restrict__ mb = membuf + ((NCH - 1) & 1) * XCHUNK_ELEMS;
            const int t0 = (NCH - 1) * CH;
            #pragma unroll
            for (int s = w * 32; s < w * 32 + 32; s++) {
                const float m = mb[s * 32 + lane];
                const size_t off = (size_t)(t0 + s) * B_NEUR + b;
                __stcs(O_mem + off, m);
                __stcs(O_spk + off, (__fsub_rn(m, 1.0f) > 0.0f) ? 1.0f : 0.0f);
            }
        }
    } else {
        // ======== exc/inh writers (r 4..7): map staged chunk c, 32 steps ====
        const int w = r - 4;
        __syncthreads();            // prologue barrier
        for (int c = 0; c < NCH; c++) {
            const float2* __restrict__ xb = xbuf + (c % XRING) * XCHUNK_ELEMS;
            const int t0 = c * CH;
            #pragma unroll
            for (int s = w * 32; s < w * 32 + 32; s++) {
                const float2 v = xb[s * 32 + lane];
                const float exc = __fmaf_rn(v.y, w01, __fmul_rn(v.x, w00));
                const size_t off = (size_t)(t0 + s) * B_NEUR + b;
                __stcs(O_exc + off, exc);
                __stcs(O_inh + off, 0.0f);   // winh==0: w_inh*inh == +0 exactly
            }
            __syncthreads();
        }
    }
}

extern "C" void kernel_launch(void* const* d_in, const int* in_sizes, int n_in,
                              void* d_out, int out_size)
{
    const float* x     = (const float*)d_in[0];
    const float* w_exc = (const float*)d_in[1];
    const float* w_inh = (const float*)d_in[2];
    float* out         = (float*)d_out;
    (void)in_sizes; (void)n_in; (void)out_size;

    static int smem_set = 0;
    if (!smem_set) {
        cudaFuncSetAttribute(fmfm_onepass,
                             cudaFuncAttributeMaxDynamicSharedMemorySize,
                             SMEM_BYTES);
        smem_set = 1;
    }
    fmfm_onepass<<<B_NEUR / 32, THREADS, SMEM_BYTES>>>(x, w_exc, w_inh, out);
}

// round 17
// speedup vs baseline: 1.1860x; 1.0588x over previous
#include <cuda_runtime.h>
#include <cstdint>

// FMFMNeuronInhib: T=4096, B=4096.  x:[T][B][2] f32.  out = spk|exc|inh|mem.
//
// Decoupled producer/consumer pipeline (no block-wide barriers in steady
// state). 128 blocks x 448 threads (14 warps), 32 neurons per block, one
// block per SM, ~144 KB dynamic smem:
//   wids 8-12 : cp.async(8B) producers -> xbuf ring (3 x 32KB), warp-elected
//               mbarrier arrive after per-warp wait_group
//   wid  13   : exact mem-recurrence chain: consumes xbuf, produces membuf
//               ring (3 x 16KB)
//   wids 0-3  : mem/spk writers: consume membuf
//   wids 4-7  : exc/inh writers: consume xbuf
// Sync: per-slot (full, empty) mbarriers; chunk c -> slot c%3, FULL phase
// (c/3)&1, EMPTY-wait phase ((c/3)-1)&1 (skipped for first ring cycle).
// x read from DRAM exactly once; traffic = 384 MB. Arithmetic byte-identical
// to prior passing kernels. Fast path exact for winh==0; fallback otherwise.

#define T_STEPS 4096
#define B_NEUR  4096
#define CH      128                  // steps per chunk
#define NCH     (T_STEPS / CH)       // 32
#define XRING   3
#define MRING   3
#define THREADS 448

#define XCHUNK_ELEMS (CH * 32)                        // float2 per chunk
#define XBYTES   (XRING * XCHUNK_ELEMS * 8)           // 98304
#define MBYTES   (MRING * XCHUNK_ELEMS * 4)           // 49152
#define BARO     (XBYTES + MBYTES)                    // 147456
// barriers: xfull[3] | xempty[3] | mfull[3] | mempty[3]  (8 B each)
#define SMEM_BYTES (BARO + 128)

#define CP_ASYNC8(sa, g) \
    asm volatile("cp.async.ca.shared.global [%0], [%1], 8;" :: "r"(sa), "l"(g))
#define CP_COMMIT()  asm volatile("cp.async.commit_group;" ::: "memory")
#define CP_WAIT1()   asm volatile("cp.async.wait_group 1;" ::: "memory")

#define MBAR_INIT(a, n) \
    asm volatile("mbarrier.init.shared.b64 [%0], %1;" :: "r"(a), "r"(n) : "memory")
#define MBAR_ARRIVE(a) \
    asm volatile("mbarrier.arrive.shared.b64 _, [%0];" :: "r"(a) : "memory")

__device__ __forceinline__ void mbar_wait(uint32_t a, uint32_t ph) {
    uint32_t done;
    do {
        asm volatile(
            "{\n\t.reg .pred p;\n\t"
            "mbarrier.try_wait.parity.acquire.cta.shared::cta.b64 p, [%1], %2, 0x989680;\n\t"
            "selp.b32 %0, 1, 0, p;\n\t}"
            : "=r"(done) : "r"(a), "r"(ph) : "memory");
    } while (!done);
}

__global__ __launch_bounds__(THREADS, 1)
void fmfm_decoupled(const float* __restrict__ x,
                    const float* __restrict__ w_exc,
                    const float* __restrict__ w_inh_p,
                    float* __restrict__ out)
{
    extern __shared__ __align__(128) char dyn[];
    float2* const xbuf   = reinterpret_cast<float2*>(dyn);            // [XRING][CH*32]
    float*  const membuf = reinterpret_cast<float*>(dyn + XBYTES);    // [MRING][CH*32]
    const uint32_t barb  = (uint32_t)__cvta_generic_to_shared(dyn) + BARO;
    const uint32_t XFULL = barb, XEMPTY = barb + 24, MFULL = barb + 48, MEMPTY = barb + 72;

    const int tid  = threadIdx.x;
    const int wid  = tid >> 5;
    const int lane = tid & 31;
    const int b    = blockIdx.x * 32 + lane;

    const float w00  = w_exc[0];
    const float w01  = w_exc[1];
    const float winh = *w_inh_p;

    float* __restrict__ O_spk = out;
    float* __restrict__ O_exc = out + (size_t)T_STEPS * B_NEUR;
    float* __restrict__ O_inh = out + 2ull * T_STEPS * B_NEUR;
    float* __restrict__ O_mem = out + 3ull * T_STEPS * B_NEUR;

    const float2* __restrict__ x2 = reinterpret_cast<const float2*>(x);
    const float2* __restrict__ xw = x2 + b;

    // ---------------- generic fallback (winh != 0): exact, never taken here
    if (winh != 0.0f) {
        if (tid < 32) {
            float mem = 0.0f, inh = 0.0f;
            for (int t = 0; t < T_STEPS; t++) {
                const float2 v = xw[(size_t)t * B_NEUR];
                inh = __fmaf_rn(0.6f, inh, v.x);
                const float exc = __fmaf_rn(v.y, w01, __fmul_rn(v.x, w00));
                const float cur = __fmaf_rn(winh, inh, exc);
                const float reset = (mem > 1.0f) ? 1.0f : 0.0f;
                mem = __fsub_rn(__fadd_rn(__fmul_rn(0.9f, mem), cur), reset);
                const size_t off = (size_t)t * B_NEUR + b;
                O_spk[off] = (__fsub_rn(mem, 1.0f) > 0.0f) ? 1.0f : 0.0f;
                O_exc[off] = exc;
                O_inh[off] = __fmul_rn(winh, inh);
                O_mem[off] = mem;
            }
        }
        return;
    }

    // ---------------- init barriers ----------------
    if (tid == 0) {
        #pragma unroll
        for (int i = 0; i < 3; i++) {
            MBAR_INIT(XFULL  + i * 8, 5);   // 5 producer warps (elected lane)
            MBAR_INIT(XEMPTY + i * 8, 5);   // chain warp + 4 exc warps
            MBAR_INIT(MFULL  + i * 8, 1);   // chain warp
            MBAR_INIT(MEMPTY + i * 8, 4);   // 4 mem/spk warps
        }
    }
    __syncthreads();    // the only block-wide barrier

    if (wid >= 8 && wid <= 12) {
        // ======== producers: cp.async x chunk stream into xbuf ring ========
        const int p = wid - 8;
        // prologue: fill chunks 0,1
        #pragma unroll
        for (int k = 0; k < 2; k++) {
            float2* __restrict__ xb = xbuf + k * XCHUNK_ELEMS;
            for (int s = p; s < CH; s += 5) {
                const float2* g = xw + (size_t)(k * CH + s) * B_NEUR;
                const uint32_t sa =
                    (uint32_t)__cvta_generic_to_shared(&xb[s * 32 + lane]);
                CP_ASYNC8(sa, g);
            }
            CP_COMMIT();
        }
        CP_WAIT1();                       // chunk 0 resident (this warp's copies)
        __syncwarp();
        if (lane == 0) MBAR_ARRIVE(XFULL + 0);
        for (int c = 0; c < NCH; c++) {
            const int cf = c + 2;
            if (cf < NCH) {
                if (cf >= XRING)          // slot reused: wait consumers' release
                    mbar_wait(XEMPTY + (cf % XRING) * 8,
                              (uint32_t)(((cf / XRING) - 1) & 1));
                const int t0 = cf * CH;
                float2* __restrict__ xb = xbuf + (cf % XRING) * XCHUNK_ELEMS;
                for (int s = p; s < CH; s += 5) {
                    const float2* g = xw + (size_t)(t0 + s) * B_NEUR;
                    const uint32_t sa =
                        (uint32_t)__cvta_generic_to_shared(&xb[s * 32 + lane]);
                    CP_ASYNC8(sa, g);
                }
            }
            CP_COMMIT();                  // (possibly empty) keeps group count uniform
            CP_WAIT1();                   // all but newest -> chunk c+1 resident
            __syncwarp();
            if (lane == 0 && c + 1 < NCH) MBAR_ARRIVE(XFULL + ((c + 1) % XRING) * 8);
        }
    } else if (wid == 13) {
        // ======== chain warp: exact mem recurrence ========
        float mem = 0.0f;
        for (int c = 0; c < NCH; c++) {
            const uint32_t ph = (uint32_t)((c / XRING) & 1);
            mbar_wait(XFULL + (c % XRING) * 8, ph);
            if (c >= MRING)               // membuf slot reused: wait writers
                mbar_wait(MEMPTY + (c % MRING) * 8,
                          (uint32_t)(((c / MRING) - 1) & 1));
            const float2* __restrict__ xb = xbuf + (c % XRING) * XCHUNK_ELEMS;
            float* __restrict__       mb = membuf + (c % MRING) * XCHUNK_ELEMS;
            #pragma unroll
            for (int k = 0; k < CH; k += 16) {
                float2 v[16];
                #pragma unroll
                for (int i = 0; i < 16; i++)
                    v[i] = xb[(k + i) * 32 + lane];
                #pragma unroll
                for (int i = 0; i < 16; i++) {
                    // cur == exc exactly when winh==0
                    const float cur = __fmaf_rn(v[i].y, w01, __fmul_rn(v[i].x, w00));
                    const float reset = (mem > 1.0f) ? 1.0f : 0.0f;
                    mem = __fsub_rn(__fadd_rn(__fmul_rn(0.9f, mem), cur), reset);
                    mb[(k + i) * 32 + lane] = mem;
                }
            }
            __syncwarp();
            if (lane == 0) {
                MBAR_ARRIVE(XEMPTY + (c % XRING) * 8);  // done reading x chunk
                MBAR_ARRIVE(MFULL + (c % MRING) * 8);   // membuf slot published
            }
        }
    } else if (wid < 4) {
        // ======== mem/spk writers: consume membuf ring ========
        const int w = wid;
        for (int c = 0; c < NCH; c++) {
            mbar_wait(MFULL + (c % MRING) * 8, (uint32_t)((c / MRING) & 1));
            const float* __restrict__ mb = membuf + (c % MRING) * XCHUNK_ELEMS;
            const int t0 = c * CH;
            #pragma unroll
            for (int s = w * 32; s < w * 32 + 32; s++) {
                const float m = mb[s * 32 + lane];
                const size_t off = (size_t)(t0 + s) * B_NEUR + b;
                __stcs(O_mem + off, m);
                __stcs(O_spk + off, (__fsub_rn(m, 1.0f) > 0.0f) ? 1.0f : 0.0f);
            }
            __syncwarp();
            if (lane == 0) MBAR_ARRIVE(MEMPTY + (c % MRING) * 8);
        }
    } else {
        // ======== exc/inh writers: consume xbuf ring ========
        const int w = wid - 4;
        for (int c = 0; c < NCH; c++) {
            mbar_wait(XFULL + (c % XRING) * 8, (uint32_t)((c / XRING) & 1));
            const float2* __restrict__ xb = xbuf + (c % XRING) * XCHUNK_ELEMS;
            const int t0 = c * CH;
            #pragma unroll
            for (int s = w * 32; s < w * 32 + 32; s++) {
                const float2 v = xb[s * 32 + lane];
                const float exc = __fmaf_rn(v.y, w01, __fmul_rn(v.x, w00));
                const size_t off = (size_t)(t0 + s) * B_NEUR + b;
                __stcs(O_exc + off, exc);
                __stcs(O_inh + off, 0.0f);   // winh==0: w_inh*inh == +0 exactly
            }
            __syncwarp();
            if (lane == 0) MBAR_ARRIVE(XEMPTY + (c % XRING) * 8);
        }
    }
}

extern "C" void kernel_launch(void* const* d_in, const int* in_sizes, int n_in,
                              void* d_out, int out_size)
{
    const float* x     = (const float*)d_in[0];
    const float* w_exc = (const float*)d_in[1];
    const float* w_inh = (const float*)d_in[2];
    float* out         = (float*)d_out;
    (void)in_sizes; (void)n_in; (void)out_size;

    static int smem_set = 0;
    if (!smem_set) {
        cudaFuncSetAttribute(fmfm_decoupled,
                             cudaFuncAttributeMaxDynamicSharedMemorySize,
                             SMEM_BYTES);
        smem_set = 1;
    }
    fmfm_decoupled<<<B_NEUR / 32, THREADS, SMEM_BYTES>>>(x, w_exc, w_inh, out);
}